// round 1
// baseline (speedup 1.0000x reference)
#include <cuda_runtime.h>
#include <math.h>

#define NT     20000
#define K1DIM  20001
#define BB     64
#define FF     128
#define TT     16
#define H4     1024
#define HD     256
#define EPSF   1e-5f

// ---------------- scratch layout (single __device__ array, no allocs) ----------
// zeroed region first: counts + 4 accumulator buffers
#define OFF_CNT    0           // 64*20000        = 1,280,000
#define OFF_ACC1   1280000     // 64*1024         = 65,536
#define OFF_ACC2   1345536     // 64*1024
#define OFF_ACC3   1411072     // 64*256          = 16,384
#define OFF_ACC4   1427456     // 64*1024
#define ZERO_N     1492992
#define OFF_YT     1492992     // 20001*64        = 1,280,064   yT[k][b]
#define OFF_HT     2773056     // 1024*64                         hT[j][b]
#define OFF_H2T    2838592     // 1024*64
#define OFF_ENCT   2904128     // 256*64
#define OFF_D1T    2920512     // 1024*64
#define OFF_STATS  2986048     // 64*2 (mu, rstd)
#define SCRATCH_N  2986176

__device__ __align__(16) float g_scratch[SCRATCH_N];

// ---------------- packed fp32x2 FMA (Blackwell FFMA2) --------------------------
__device__ __forceinline__ void ffma2(unsigned long long& c,
                                      unsigned long long a,
                                      unsigned long long b) {
    asm("fma.rn.f32x2 %0, %1, %2, %0;" : "+l"(c) : "l"(a), "l"(b));
}

__device__ __forceinline__ float gelu_exact(float x) {
    return 0.5f * x * (1.0f + erff(x * 0.70710678118654752f));
}

// ---------------- K0: zero counts + accumulators --------------------------------
__global__ void k_zero() {
    int i = blockIdx.x * blockDim.x + threadIdx.x;
    int stride = gridDim.x * blockDim.x;
    for (; i < ZERO_N; i += stride) g_scratch[i] = 0.0f;
}

// ---------------- K1: dedupe-scatter counts -------------------------------------
__global__ void k_count(const int* __restrict__ tags) {
    int r = blockIdx.x * blockDim.x + threadIdx.x;   // (b, f) row
    if (r >= BB * FF) return;
    int b = r / FF;
    const int* t = tags + r * TT;
    int v[TT];
#pragma unroll
    for (int i = 0; i < TT; i++) v[i] = t[i];
    float* cnt = &g_scratch[OFF_CNT] + (long long)b * NT;
#pragma unroll
    for (int i = 0; i < TT; i++) {
        bool dup = false;
#pragma unroll
        for (int j = 0; j < TT; j++)
            if (j < i && v[j] == v[i]) dup = true;
        if (!dup) atomicAdd(&cnt[v[i]], 1.0f);
    }
}

// ---------------- K2: per-batch mean / rstd over 20000 counts -------------------
__global__ void k_stats() {
    int b = blockIdx.x;
    const float* cnt = &g_scratch[OFF_CNT] + (long long)b * NT;
    float s = 0.0f, s2 = 0.0f;
    for (int i = threadIdx.x; i < NT; i += blockDim.x) {
        float v = cnt[i];
        s += v; s2 += v * v;
    }
    __shared__ float sh[256], sh2[256];
    sh[threadIdx.x] = s; sh2[threadIdx.x] = s2;
    __syncthreads();
    for (int o = 128; o > 0; o >>= 1) {
        if (threadIdx.x < o) { sh[threadIdx.x] += sh[threadIdx.x + o]; sh2[threadIdx.x] += sh2[threadIdx.x + o]; }
        __syncthreads();
    }
    if (threadIdx.x == 0) {
        float mu  = sh[0] / (float)NT;
        float var = sh2[0] / (float)NT - mu * mu;
        g_scratch[OFF_STATS + b * 2]     = mu;
        g_scratch[OFF_STATS + b * 2 + 1] = rsqrtf(var + EPSF);
    }
}

// ---------------- K3: build y (to d_out) and yT (transposed GEMM operand) ------
__global__ void k_y(const float* __restrict__ fc, const float* __restrict__ lg,
                    const float* __restrict__ lb, float* __restrict__ yout) {
    int b = blockIdx.y;
    int k = blockIdx.x * blockDim.x + threadIdx.x;
    if (k >= K1DIM) return;
    float val;
    if (k == 0) {
        val = fc[b] / 100.0f;
    } else {
        float mu = g_scratch[OFF_STATS + b * 2];
        float r  = g_scratch[OFF_STATS + b * 2 + 1];
        float c  = g_scratch[OFF_CNT + (long long)b * NT + (k - 1)];
        val = (c - mu) * r * lg[k - 1] + lb[k - 1];
    }
    yout[(long long)b * K1DIM + k] = val;
    g_scratch[OFF_YT + (long long)k * BB + b] = val;
}

// ---------------- generic tiled GEMM:  out[64][N] (+)= AT[K][64]^T @ W[K][N] ----
// block: 256 thr; j-tile = 128 cols; thread = (jg = tid&31 -> j = jbase+jg+32*ji,
// bg = tid>>5 -> b = bg*8 + 2*bi). 32 fp32 accumulators as 16 packed f32x2.
// mode 0: atomicAdd partial (split-K).   mode 1: direct store + bias.
__global__ __launch_bounds__(256, 2)
void k_gemm(int at_off, const float* __restrict__ W, int out_off,
            float* __restrict__ out_ext, const float* __restrict__ bias,
            int K, int N, int kPerSlice, int mode) {
    __shared__ float2 ws[16][128];   // (w, w) duplicated pairs
    __shared__ float2 ys[16][32];    // (y_b, y_{b+1}) pairs
    const float* AT = &g_scratch[at_off];
    float* out = out_ext ? out_ext : &g_scratch[out_off];

    int jbase  = blockIdx.x * 128;
    int kstart = blockIdx.y * kPerSlice;
    int kend   = min(kstart + kPerSlice, K);
    int tid = threadIdx.x;
    int jg = tid & 31, bg = tid >> 5;

    unsigned long long acc[4][4];
#pragma unroll
    for (int a = 0; a < 4; a++)
#pragma unroll
        for (int c = 0; c < 4; c++) acc[a][c] = 0ull;  // bit pattern of (0.f, 0.f)

    bool vecW = ((N & 3) == 0) && (jbase + 128 <= N);

    for (int kc = kstart; kc < kend; kc += 16) {
        // --- load W tile (16 x 128), duplicated into float2 lanes ---
        {
            int row = tid >> 4;
            int col = (tid & 15) * 8;
            int kg  = kc + row;
            float v[8];
            if (kg < kend && vecW) {
                const float4* p = reinterpret_cast<const float4*>(&W[(long long)kg * N + jbase + col]);
                float4 a0 = p[0], a1 = p[1];
                v[0]=a0.x; v[1]=a0.y; v[2]=a0.z; v[3]=a0.w;
                v[4]=a1.x; v[5]=a1.y; v[6]=a1.z; v[7]=a1.w;
            } else {
#pragma unroll
                for (int i = 0; i < 8; i++) {
                    int j = jbase + col + i;
                    v[i] = (kg < kend && j < N) ? W[(long long)kg * N + j] : 0.0f;
                }
            }
#pragma unroll
            for (int i = 0; i < 8; i++) ws[row][col + i] = make_float2(v[i], v[i]);

            // --- load AT tile (16 x 64) as b-pairs ---
            int ycol = (tid & 15) * 4;
            float4 yv = make_float4(0.f, 0.f, 0.f, 0.f);
            if (kg < kend)
                yv = *reinterpret_cast<const float4*>(&AT[(long long)kg * BB + ycol]);
            ys[row][(ycol >> 1)]     = make_float2(yv.x, yv.y);
            ys[row][(ycol >> 1) + 1] = make_float2(yv.z, yv.w);
        }
        __syncthreads();

#pragma unroll
        for (int kk = 0; kk < 16; kk++) {
            unsigned long long wv[4];
#pragma unroll
            for (int ji = 0; ji < 4; ji++)
                wv[ji] = *reinterpret_cast<const unsigned long long*>(&ws[kk][jg + 32 * ji]);
            ulonglong2 y01 = *reinterpret_cast<const ulonglong2*>(&ys[kk][bg * 4]);
            ulonglong2 y23 = *reinterpret_cast<const ulonglong2*>(&ys[kk][bg * 4 + 2]);
            unsigned long long yv[4] = { y01.x, y01.y, y23.x, y23.y };
#pragma unroll
            for (int ji = 0; ji < 4; ji++)
#pragma unroll
                for (int bi = 0; bi < 4; bi++)
                    ffma2(acc[ji][bi], wv[ji], yv[bi]);
        }
        __syncthreads();
    }

    // --- epilogue ---
#pragma unroll
    for (int ji = 0; ji < 4; ji++) {
        int j = jbase + jg + 32 * ji;
        if (j >= N) continue;
        float bv = bias ? bias[j] : 0.0f;
#pragma unroll
        for (int bi = 0; bi < 4; bi++) {
            int b = bg * 8 + bi * 2;
            float2 f = *reinterpret_cast<float2*>(&acc[ji][bi]);
            if (mode == 0) {
                atomicAdd(&out[(long long)b * N + j],       f.x);
                atomicAdd(&out[(long long)(b + 1) * N + j], f.y);
            } else {
                out[(long long)b * N + j]       = f.x + bv;
                out[(long long)(b + 1) * N + j] = f.y + bv;
            }
        }
    }
}

// ---------------- K5: bias + GELU + LayerNorm(1024) -> hT[j][b] ------------------
__global__ void k_eln(const float* __restrict__ b1, const float* __restrict__ lg,
                      const float* __restrict__ lb) {
    int b = blockIdx.x;
    __shared__ float vals[H4];
    __shared__ float red[256];
    const float* acc = &g_scratch[OFF_ACC1] + (long long)b * H4;
    float s = 0.0f;
    for (int j = threadIdx.x; j < H4; j += 256) {
        float x = acc[j] + b1[j];
        float g = gelu_exact(x);
        vals[j] = g; s += g;
    }
    red[threadIdx.x] = s; __syncthreads();
    for (int o = 128; o > 0; o >>= 1) {
        if (threadIdx.x < o) red[threadIdx.x] += red[threadIdx.x + o];
        __syncthreads();
    }
    float mu = red[0] / (float)H4;
    __syncthreads();
    float s2 = 0.0f;
    for (int j = threadIdx.x; j < H4; j += 256) { float d = vals[j] - mu; s2 += d * d; }
    red[threadIdx.x] = s2; __syncthreads();
    for (int o = 128; o > 0; o >>= 1) {
        if (threadIdx.x < o) red[threadIdx.x] += red[threadIdx.x + o];
        __syncthreads();
    }
    float r = rsqrtf(red[0] / (float)H4 + EPSF);
    for (int j = threadIdx.x; j < H4; j += 256)
        g_scratch[OFF_HT + (long long)j * BB + b] = (vals[j] - mu) * r * lg[j] + lb[j];
}

// ---------------- bias + GELU + transpose (acc[64][N] -> out[N][64]) ------------
__global__ void k_gelu_t(int in_off, const float* __restrict__ bias, int out_off, int N) {
    int idx = blockIdx.x * blockDim.x + threadIdx.x;
    if (idx >= BB * N) return;
    int b = idx / N, j = idx - b * N;
    float x = g_scratch[in_off + idx] + bias[j];
    g_scratch[out_off + (long long)j * BB + b] = gelu_exact(x);
}

// ---------------- enc epilogue: bias, write d_out + encT ------------------------
__global__ void k_enc(const float* __restrict__ be2, float* __restrict__ enc_out) {
    int idx = blockIdx.x * blockDim.x + threadIdx.x;
    if (idx >= BB * HD) return;
    int b = idx / HD, j = idx - b * HD;
    float v = g_scratch[OFF_ACC3 + idx] + be2[j];
    enc_out[idx] = v;
    g_scratch[OFF_ENCT + (long long)j * BB + b] = v;
}

// --------------------------------------------------------------------------------
extern "C" void kernel_launch(void* const* d_in, const int* in_sizes, int n_in,
                              void* d_out, int out_size) {
    const int*   tags  = (const int*)d_in[0];
    const float* fc    = (const float*)d_in[1];
    const float* ln_g  = (const float*)d_in[2];
    const float* ln_b  = (const float*)d_in[3];
    const float* w1    = (const float*)d_in[4];
    const float* b1    = (const float*)d_in[5];
    const float* ln2_g = (const float*)d_in[6];
    const float* ln2_b = (const float*)d_in[7];
    const float* we1   = (const float*)d_in[8];
    const float* be1   = (const float*)d_in[9];
    const float* we2   = (const float*)d_in[10];
    const float* be2   = (const float*)d_in[11];
    const float* wd1   = (const float*)d_in[12];
    const float* bd1   = (const float*)d_in[13];
    const float* wd2   = (const float*)d_in[14];
    const float* bd2   = (const float*)d_in[15];

    float* out     = (float*)d_out;
    float* y_out   = out;                       // [64][20001]
    float* enc_out = out + (long long)BB * K1DIM;           // [64][256]
    float* dec_out = enc_out + (long long)BB * HD;          // [64][20001]

    k_zero<<<512, 256>>>();
    k_count<<<(BB * FF + 127) / 128, 128>>>(tags);
    k_stats<<<BB, 256>>>();
    k_y<<<dim3((K1DIM + 255) / 256, BB), 256>>>(fc, ln_g, ln_b, y_out);

    // GEMM1: y[64,20001] @ w1[20001,1024] -> acc1 (split-K, 8 jt x 19 ks)
    k_gemm<<<dim3(8, 19), 256>>>(OFF_YT, w1, OFF_ACC1, nullptr, nullptr,
                                 K1DIM, H4, 1056, 0);
    k_eln<<<BB, 256>>>(b1, ln2_g, ln2_b);

    // GEMM2: h[64,1024] @ we1[1024,1024] -> acc2 (8 jt x 8 ks)
    k_gemm<<<dim3(8, 8), 256>>>(OFF_HT, we1, OFF_ACC2, nullptr, nullptr,
                                H4, H4, 128, 0);
    k_gelu_t<<<(BB * H4 + 255) / 256, 256>>>(OFF_ACC2, be1, OFF_H2T, H4);

    // GEMM3: h2[64,1024] @ we2[1024,256] -> acc3 (2 jt x 16 ks)
    k_gemm<<<dim3(2, 16), 256>>>(OFF_H2T, we2, OFF_ACC3, nullptr, nullptr,
                                 H4, HD, 64, 0);
    k_enc<<<(BB * HD + 255) / 256, 256>>>(be2, enc_out);

    // GEMM4: enc[64,256] @ wd1[256,1024] -> acc4 (8 jt x 2 ks)
    k_gemm<<<dim3(8, 2), 256>>>(OFF_ENCT, wd1, OFF_ACC4, nullptr, nullptr,
                                HD, H4, 128, 0);
    k_gelu_t<<<(BB * H4 + 255) / 256, 256>>>(OFF_ACC4, bd1, OFF_D1T, H4);

    // GEMM5: d1[64,1024] @ wd2[1024,20001] -> dec (direct store + bias, 157 jt)
    k_gemm<<<dim3(157, 1), 256>>>(OFF_D1T, wd2, 0, dec_out, bd2,
                                  H4, K1DIM, 1024, 1);
}

// round 2
// speedup vs baseline: 1.9128x; 1.9128x over previous
#include <cuda_runtime.h>
#include <math.h>

#define NT     20000
#define K1DIM  20001
#define BB     64
#define H4     1024
#define HD     256
#define EPSF   1e-5f
#define FF     128
#define TT     16

// split-K slice counts
#define S1 74
#define S2 16
#define S3 32
#define S4 8
#define S5 4
#define NS5 20002   // padded (even) partial stride for GEMM5

// ---------------- scratch layout (floats) ---------------------------------
#define OFF_CNT    0            // 64*20000 = 1,280,000
#define OFF_YT     1280000      // 20001*64 = 1,280,064
#define OFF_HT     2560064      // 1024*64
#define OFF_H2T    2625600      // 1024*64
#define OFF_ENCT   2691136      // 256*64
#define OFF_D1T    2707520      // 1024*64
#define OFF_STATS  2773056      // 64*2
#define OFF_P1     2773184      // 74*64*1024 = 4,849,664
#define OFF_P2     7622848      // 16*64*1024 = 1,048,576
#define OFF_P3     8671424      // 32*64*256  =   524,288
#define OFF_P4     9195712      // 8*64*1024  =   524,288
#define OFF_P5     9720000      // 4*64*20002 = 5,120,512
#define SCRATCH_N  14840512

__device__ __align__(16) float g_scratch[SCRATCH_N];

// ---------------- packed fp32x2 FMA ----------------------------------------
__device__ __forceinline__ void ffma2(unsigned long long& c,
                                      unsigned long long a,
                                      unsigned long long b) {
    asm("fma.rn.f32x2 %0, %1, %2, %0;" : "+l"(c) : "l"(a), "l"(b));
}
__device__ __forceinline__ unsigned long long dup2(float v) {
    float2 t; t.x = v; t.y = v;
    return *reinterpret_cast<unsigned long long*>(&t);
}
__device__ __forceinline__ float gelu_exact(float x) {
    return 0.5f * x * (1.0f + erff(x * 0.70710678118654752f));
}

// ---------------- K0: zero tag counts --------------------------------------
__global__ void k_zero() {
    int i = blockIdx.x * blockDim.x + threadIdx.x;
    int stride = gridDim.x * blockDim.x;
    for (; i < BB * NT; i += stride) g_scratch[OFF_CNT + i] = 0.0f;
}

// ---------------- K1: dedupe-scatter counts --------------------------------
__global__ void k_count(const int* __restrict__ tags) {
    int r = blockIdx.x * blockDim.x + threadIdx.x;
    if (r >= BB * FF) return;
    int b = r / FF;
    const int* t = tags + r * TT;
    int v[TT];
#pragma unroll
    for (int i = 0; i < TT; i++) v[i] = t[i];
    float* cnt = &g_scratch[OFF_CNT] + (long long)b * NT;
#pragma unroll
    for (int i = 0; i < TT; i++) {
        bool dup = false;
#pragma unroll
        for (int j = 0; j < TT; j++)
            if (j < i && v[j] == v[i]) dup = true;
        if (!dup) atomicAdd(&cnt[v[i]], 1.0f);
    }
}

// ---------------- K2: per-batch mean / rstd --------------------------------
__global__ void k_stats() {
    int b = blockIdx.x;
    const float* cnt = &g_scratch[OFF_CNT] + (long long)b * NT;
    float s = 0.0f, s2 = 0.0f;
    for (int i = threadIdx.x; i < NT; i += blockDim.x) {
        float v = cnt[i];
        s += v; s2 += v * v;
    }
    __shared__ float sh[256], sh2[256];
    sh[threadIdx.x] = s; sh2[threadIdx.x] = s2;
    __syncthreads();
    for (int o = 128; o > 0; o >>= 1) {
        if (threadIdx.x < o) { sh[threadIdx.x] += sh[threadIdx.x + o]; sh2[threadIdx.x] += sh2[threadIdx.x + o]; }
        __syncthreads();
    }
    if (threadIdx.x == 0) {
        float mu  = sh[0] / (float)NT;
        float var = sh2[0] / (float)NT - mu * mu;
        g_scratch[OFF_STATS + b * 2]     = mu;
        g_scratch[OFF_STATS + b * 2 + 1] = rsqrtf(var + EPSF);
    }
}

// ---------------- K3: build y + coalesced transpose to yT -------------------
__global__ void k_y(const float* __restrict__ fc, const float* __restrict__ lg,
                    const float* __restrict__ lb, float* __restrict__ yout) {
    __shared__ float tile[64][65];
    int kbase = blockIdx.x * 64;
    int tx = threadIdx.x & 63;       // k within tile (phase1) / b (phase2)
    int ty = threadIdx.x >> 6;       // 0..3
    // phase 1: read counts (coalesced), compute y, write y (coalesced)
#pragma unroll
    for (int i = 0; i < 16; i++) {
        int b = i * 4 + ty;
        int k = kbase + tx;
        if (k < K1DIM) {
            float val;
            if (k == 0) {
                val = fc[b] * 0.01f;
            } else {
                float mu = g_scratch[OFF_STATS + b * 2];
                float r  = g_scratch[OFF_STATS + b * 2 + 1];
                float c  = g_scratch[OFF_CNT + (long long)b * NT + (k - 1)];
                val = (c - mu) * r * lg[k - 1] + lb[k - 1];
            }
            yout[(long long)b * K1DIM + k] = val;
            tile[tx][b] = val;
        }
    }
    __syncthreads();
    // phase 2: write yT rows (coalesced)
#pragma unroll
    for (int i = 0; i < 16; i++) {
        int kl = i * 4 + ty;
        int k  = kbase + kl;
        if (k < K1DIM)
            g_scratch[OFF_YT + (long long)k * BB + tx] = tile[kl][tx];
    }
}

// ---------------- tiled GEMM: partial[s][64][Ns] = AT[K][64]^T @ W[K][N] ----
// 128 threads; block tile 128 j x 64 b; thread tile 8 j (4 pairs) x 8 b.
__global__ __launch_bounds__(128, 3)
void k_gemm(int at_off, const float* __restrict__ W, int p_off,
            int K, int N, int Ns, int kPerSlice) {
    __shared__ float ws[16][128];
    __shared__ float ys[16][64];
    const float* AT = &g_scratch[at_off];

    int jbase  = blockIdx.x * 128;
    int s      = blockIdx.y;
    int kstart = s * kPerSlice;
    int kend   = min(kstart + kPerSlice, K);
    int tid = threadIdx.x;
    int jg = tid & 15;         // 16 j-groups
    int bg = tid >> 4;         // 8 b-groups

    unsigned long long acc[4][8];
#pragma unroll
    for (int p = 0; p < 4; p++)
#pragma unroll
        for (int i = 0; i < 8; i++) acc[p][i] = 0ull;

    bool vecW = ((N & 3) == 0) && (jbase + 128 <= N);

    for (int kc = kstart; kc < kend; kc += 16) {
        // load W tile 16 x 128
        if (vecW) {
#pragma unroll
            for (int i = 0; i < 4; i++) {
                int idx = tid + 128 * i;          // 0..511 float4s
                int row = idx >> 5;               // 0..15
                int col = (idx & 31) * 4;
                int kg  = kc + row;
                float4 v = make_float4(0.f, 0.f, 0.f, 0.f);
                if (kg < kend)
                    v = *reinterpret_cast<const float4*>(&W[(long long)kg * N + jbase + col]);
                *reinterpret_cast<float4*>(&ws[row][col]) = v;
            }
        } else {
#pragma unroll
            for (int i = 0; i < 16; i++) {
                int idx = tid + 128 * i;          // 0..2047
                int row = idx >> 7;
                int col = idx & 127;
                int kg  = kc + row;
                int j   = jbase + col;
                ws[row][col] = (kg < kend && j < N) ? W[(long long)kg * N + j] : 0.0f;
            }
        }
        // load y tile 16 x 64
#pragma unroll
        for (int i = 0; i < 2; i++) {
            int idx = tid + 128 * i;              // 0..255 float4s
            int row = idx >> 4;
            int col = (idx & 15) * 4;
            int kg  = kc + row;
            float4 v = make_float4(0.f, 0.f, 0.f, 0.f);
            if (kg < kend)
                v = *reinterpret_cast<const float4*>(&AT[(long long)kg * BB + col]);
            *reinterpret_cast<float4*>(&ys[row][col]) = v;
        }
        __syncthreads();

#pragma unroll
        for (int kk = 0; kk < 16; kk++) {
            unsigned long long wv[4];
#pragma unroll
            for (int p = 0; p < 4; p++)
                wv[p] = *reinterpret_cast<const unsigned long long*>(&ws[kk][2 * (jg + 16 * p)]);
            float4 ya = *reinterpret_cast<const float4*>(&ys[kk][bg * 8]);
            float4 yb = *reinterpret_cast<const float4*>(&ys[kk][bg * 8 + 4]);
            unsigned long long yd[8];
            yd[0] = dup2(ya.x); yd[1] = dup2(ya.y); yd[2] = dup2(ya.z); yd[3] = dup2(ya.w);
            yd[4] = dup2(yb.x); yd[5] = dup2(yb.y); yd[6] = dup2(yb.z); yd[7] = dup2(yb.w);
#pragma unroll
            for (int p = 0; p < 4; p++)
#pragma unroll
                for (int i = 0; i < 8; i++)
                    ffma2(acc[p][i], wv[p], yd[i]);
        }
        __syncthreads();
    }

    // epilogue: store partial[s][b][j..j+1]
    float* P = &g_scratch[p_off];
#pragma unroll
    for (int p = 0; p < 4; p++) {
        int j0 = jbase + 2 * (jg + 16 * p);
        if (j0 >= N) continue;
#pragma unroll
        for (int i = 0; i < 8; i++) {
            int b = bg * 8 + i;
            *reinterpret_cast<float2*>(&P[(long long)(s * BB + b) * Ns + j0]) =
                *reinterpret_cast<float2*>(&acc[p][i]);
        }
    }
}

// ---------------- reduce P1 + bias + GELU + LayerNorm(1024) -> hT ----------
__global__ void k_eln(const float* __restrict__ b1, const float* __restrict__ lg,
                      const float* __restrict__ lb) {
    int b = blockIdx.x;
    __shared__ float vals[H4];
    __shared__ float red[256];
    float ssum = 0.0f;
    for (int j = threadIdx.x; j < H4; j += 256) {
        float x = b1[j];
        for (int sl = 0; sl < S1; sl++)
            x += g_scratch[OFF_P1 + (long long)(sl * BB + b) * H4 + j];
        float g = gelu_exact(x);
        vals[j] = g; ssum += g;
    }
    red[threadIdx.x] = ssum; __syncthreads();
    for (int o = 128; o > 0; o >>= 1) {
        if (threadIdx.x < o) red[threadIdx.x] += red[threadIdx.x + o];
        __syncthreads();
    }
    float mu = red[0] / (float)H4;
    __syncthreads();
    float s2 = 0.0f;
    for (int j = threadIdx.x; j < H4; j += 256) { float d = vals[j] - mu; s2 += d * d; }
    red[threadIdx.x] = s2; __syncthreads();
    for (int o = 128; o > 0; o >>= 1) {
        if (threadIdx.x < o) red[threadIdx.x] += red[threadIdx.x + o];
        __syncthreads();
    }
    float r = rsqrtf(red[0] / (float)H4 + EPSF);
    for (int j = threadIdx.x; j < H4; j += 256)
        g_scratch[OFF_HT + (long long)j * BB + b] = (vals[j] - mu) * r * lg[j] + lb[j];
}

// ---------------- reduce partials + bias + GELU + transpose ----------------
__global__ void k_gelu_t(int p_off, int S, const float* __restrict__ bias,
                         int out_off, int N) {
    int idx = blockIdx.x * blockDim.x + threadIdx.x;
    if (idx >= BB * N) return;
    int b = idx / N, j = idx - b * N;
    float x = bias[j];
    for (int sl = 0; sl < S; sl++)
        x += g_scratch[p_off + (long long)(sl * BB + b) * N + j];
    g_scratch[out_off + (long long)j * BB + b] = gelu_exact(x);
}

// ---------------- enc epilogue: reduce + bias -> d_out + encT --------------
__global__ void k_enc(const float* __restrict__ be2, float* __restrict__ enc_out) {
    int idx = blockIdx.x * blockDim.x + threadIdx.x;
    if (idx >= BB * HD) return;
    int b = idx / HD, j = idx - b * HD;
    float v = be2[j];
    for (int sl = 0; sl < S3; sl++)
        v += g_scratch[OFF_P3 + (long long)(sl * BB + b) * HD + j];
    enc_out[idx] = v;
    g_scratch[OFF_ENCT + (long long)j * BB + b] = v;
}

// ---------------- dec epilogue: reduce + bias -> d_out ---------------------
__global__ void k_dec(const float* __restrict__ bd2, float* __restrict__ dec_out) {
    int idx = blockIdx.x * blockDim.x + threadIdx.x;
    if (idx >= BB * K1DIM) return;
    int b = idx / K1DIM, j = idx - b * K1DIM;
    float v = bd2[j];
#pragma unroll
    for (int sl = 0; sl < S5; sl++)
        v += g_scratch[OFF_P5 + (long long)(sl * BB + b) * NS5 + j];
    dec_out[idx] = v;
}

// ---------------------------------------------------------------------------
extern "C" void kernel_launch(void* const* d_in, const int* in_sizes, int n_in,
                              void* d_out, int out_size) {
    const int*   tags  = (const int*)d_in[0];
    const float* fc    = (const float*)d_in[1];
    const float* ln_g  = (const float*)d_in[2];
    const float* ln_b  = (const float*)d_in[3];
    const float* w1    = (const float*)d_in[4];
    const float* b1    = (const float*)d_in[5];
    const float* ln2_g = (const float*)d_in[6];
    const float* ln2_b = (const float*)d_in[7];
    const float* we1   = (const float*)d_in[8];
    const float* be1   = (const float*)d_in[9];
    const float* we2   = (const float*)d_in[10];
    const float* be2   = (const float*)d_in[11];
    const float* wd1   = (const float*)d_in[12];
    const float* bd1   = (const float*)d_in[13];
    const float* wd2   = (const float*)d_in[14];
    const float* bd2   = (const float*)d_in[15];

    float* out     = (float*)d_out;
    float* y_out   = out;                          // [64][20001]
    float* enc_out = out + (long long)BB * K1DIM;  // [64][256]
    float* dec_out = enc_out + (long long)BB * HD; // [64][20001]

    k_zero<<<512, 256>>>();
    k_count<<<(BB * FF + 127) / 128, 128>>>(tags);
    k_stats<<<BB, 256>>>();
    k_y<<<(K1DIM + 63) / 64, 256>>>(fc, ln_g, ln_b, y_out);

    // G1: y[64,20001] @ w1 -> P1   (8 jt x 74 ks, kps=272)
    k_gemm<<<dim3(8, S1), 128>>>(OFF_YT, w1, OFF_P1, K1DIM, H4, H4, 272);
    k_eln<<<BB, 256>>>(b1, ln2_g, ln2_b);

    // G2: h @ we1 -> P2            (8 jt x 16 ks, kps=64)
    k_gemm<<<dim3(8, S2), 128>>>(OFF_HT, we1, OFF_P2, H4, H4, H4, 64);
    k_gelu_t<<<(BB * H4 + 255) / 256, 256>>>(OFF_P2, S2, be1, OFF_H2T, H4);

    // G3: h2 @ we2 -> P3           (2 jt x 32 ks, kps=32)
    k_gemm<<<dim3(2, S3), 128>>>(OFF_H2T, we2, OFF_P3, H4, HD, HD, 32);
    k_enc<<<(BB * HD + 255) / 256, 256>>>(be2, enc_out);

    // G4: enc @ wd1 -> P4          (8 jt x 8 ks, kps=32)
    k_gemm<<<dim3(8, S4), 128>>>(OFF_ENCT, wd1, OFF_P4, HD, H4, H4, 32);
    k_gelu_t<<<(BB * H4 + 255) / 256, 256>>>(OFF_P4, S4, bd1, OFF_D1T, H4);

    // G5: d1 @ wd2 -> P5           (157 jt x 4 ks, kps=256, padded stride)
    k_gemm<<<dim3(157, S5), 128>>>(OFF_D1T, wd2, OFF_P5, H4, K1DIM, NS5, 256);
    k_dec<<<(BB * K1DIM + 255) / 256, 256>>>(bd2, dec_out);
}